// round 17
// baseline (speedup 1.0000x reference)
#include <cuda_runtime.h>
#include <cuda_bf16.h>
#include <cstdint>
#include <math.h>

// ---------------- problem constants ----------------
#define NN 8192
#define INF_ 128
#define OUTF 64

// grid decomposition for k_main
#define M_CTA 128        // rows per CTA
#define NSPLIT 4         // K splits
#define KSPLIT (NN / NSPLIT)   // 2048 cols per CTA
#define KCHUNK 64        // cols per chunk
#define NCHUNK (KSPLIT / KCHUNK) // 32

// ---------------- device scratch (no allocs allowed) ----------------
__device__ float2 g_rowf[NN];                       // (e^f1, e^{0.2 f1})
__device__ float2 g_colf[NN];                       // (e^{f2}, e^{0.2 f2})
__device__ uint32_t g_Bf[NN * OUTF];                // 2 MB  Ht tf32, B-fragment order
__device__ float g_num[NSPLIT][NN * OUTF];          // 8 MB  partial numerators
__device__ float g_den[NSPLIT][NN];                 // partial denominators

// ---------------- smem layout for k_main ----------------
#define ADJ_STRIDE 272                     // bytes per adj row (64 ints + pad)
#define OFF_ADJ0 0
#define OFF_ADJ1 34816
#define OFF_BF0  69632                     // 16384 each: [s][f][lane][2] tf32
#define OFF_BF1  86016
#define OFF_CF0  102400                    // 512 each: 64 x float2 col factors
#define OFF_CF1  102912
#define SMEM_BYTES 103424

// ---------------- helpers ----------------
__device__ __forceinline__ uint32_t smem_u32(const void* p) {
    uint32_t a;
    asm("{ .reg .u64 t; cvta.to.shared.u64 t, %1; cvt.u32.u64 %0, t; }" : "=r"(a) : "l"(p));
    return a;
}
#define CP16(dst, src) \
    asm volatile("cp.async.cg.shared.global [%0], [%1], 16;" :: "r"(dst), "l"(src) : "memory")
#define CP_COMMIT() asm volatile("cp.async.commit_group;" ::: "memory")
#define CP_WAIT1()  asm volatile("cp.async.wait_group 1;" ::: "memory")

__device__ __forceinline__ uint32_t f2tf32(float x) {
    uint32_t r;
    asm("cvt.rna.tf32.f32 %0, %1;" : "=r"(r) : "f"(x));
    return r;
}
__device__ __forceinline__ void mma_tf32(float& d0, float& d1, float& d2, float& d3,
                                         uint32_t a0, uint32_t a1, uint32_t a2, uint32_t a3,
                                         uint32_t b0, uint32_t b1) {
    asm volatile("mma.sync.aligned.m16n8k8.row.col.f32.tf32.tf32.f32 "
                 "{%0,%1,%2,%3}, {%4,%5,%6,%7}, {%8,%9}, {%0,%1,%2,%3};"
                 : "+f"(d0), "+f"(d1), "+f"(d2), "+f"(d3)
                 : "r"(a0), "r"(a1), "r"(a2), "r"(a3), "r"(b0), "r"(b1));
}

// ---------------- fused pre-pass: h = X@W, per-node factors, B fragments ----------------
// grid 256 x 32 rows, 256 threads: 16 threads per row-pair (rows r, r+16), 4 cols each.
__global__ void __launch_bounds__(256) k_pre(const float* __restrict__ X,
                                             const float* __restrict__ W,
                                             const float* __restrict__ a) {
    extern __shared__ float dsm[];
    float* Ws = dsm;                    // [128*64]  32 KB
    float* Xs = dsm + INF_ * OUTF;      // [32*128]  16 KB
    float* as = Xs + 32 * INF_;         // [128]     512 B

    int tid = threadIdx.x;
    const float4* W4 = (const float4*)W;
    float4* Ws4 = (float4*)Ws;
#pragma unroll
    for (int q = 0; q < 8; q++) Ws4[tid + q * 256] = W4[tid + q * 256];
    int r0 = blockIdx.x * 32;
    const float4* X4 = (const float4*)(X + (size_t)r0 * INF_);
    float4* Xs4 = (float4*)Xs;
#pragma unroll
    for (int q = 0; q < 4; q++) Xs4[tid + q * 256] = X4[tid + q * 256];
    if (tid < 128) as[tid] = a[tid];
    __syncthreads();

    int r = tid >> 4;                 // 0..15 -> rows r and r+16
    int cg = (tid & 15) * 4;          // cols cg..cg+3
    int wcol = cg >> 2;
    float acc0[4], acc1[4];
#pragma unroll
    for (int j = 0; j < 4; j++) { acc0[j] = 0.f; acc1[j] = 0.f; }

    const float4* Xs4v = (const float4*)Xs;
    const float4* Ws4v = (const float4*)Ws;
#pragma unroll 4
    for (int k4 = 0; k4 < 32; k4++) {
        float4 x0 = Xs4v[r * 32 + k4];
        float4 x1 = Xs4v[(r + 16) * 32 + k4];
        float4 w;
        w = Ws4v[(k4 * 4 + 0) * 16 + wcol];
        acc0[0] += x0.x * w.x; acc0[1] += x0.x * w.y; acc0[2] += x0.x * w.z; acc0[3] += x0.x * w.w;
        acc1[0] += x1.x * w.x; acc1[1] += x1.x * w.y; acc1[2] += x1.x * w.z; acc1[3] += x1.x * w.w;
        w = Ws4v[(k4 * 4 + 1) * 16 + wcol];
        acc0[0] += x0.y * w.x; acc0[1] += x0.y * w.y; acc0[2] += x0.y * w.z; acc0[3] += x0.y * w.w;
        acc1[0] += x1.y * w.x; acc1[1] += x1.y * w.y; acc1[2] += x1.y * w.z; acc1[3] += x1.y * w.w;
        w = Ws4v[(k4 * 4 + 2) * 16 + wcol];
        acc0[0] += x0.z * w.x; acc0[1] += x0.z * w.y; acc0[2] += x0.z * w.z; acc0[3] += x0.z * w.w;
        acc1[0] += x1.z * w.x; acc1[1] += x1.z * w.y; acc1[2] += x1.z * w.z; acc1[3] += x1.z * w.w;
        w = Ws4v[(k4 * 4 + 3) * 16 + wcol];
        acc0[0] += x0.w * w.x; acc0[1] += x0.w * w.y; acc0[2] += x0.w * w.z; acc0[3] += x0.w * w.w;
        acc1[0] += x1.w * w.x; acc1[1] += x1.w * w.y; acc1[2] += x1.w * w.z; acc1[3] += x1.w * w.w;
    }

    float f1a = 0.f, f2a = 0.f, f1b = 0.f, f2b = 0.f;
#pragma unroll
    for (int j = 0; j < 4; j++) {
        f1a += acc0[j] * as[cg + j];  f2a += acc0[j] * as[64 + cg + j];
        f1b += acc1[j] * as[cg + j];  f2b += acc1[j] * as[64 + cg + j];
    }
#pragma unroll
    for (int o = 8; o > 0; o >>= 1) {
        f1a += __shfl_xor_sync(0xFFFFFFFF, f1a, o);
        f2a += __shfl_xor_sync(0xFFFFFFFF, f2a, o);
        f1b += __shfl_xor_sync(0xFFFFFFFF, f1b, o);
        f2b += __shfl_xor_sync(0xFFFFFFFF, f2b, o);
    }
    int rowA = r0 + r, rowB = r0 + r + 16;
    if ((tid & 15) == 0) {
        g_rowf[rowA] = make_float2(expf(f1a), expf(0.2f * f1a));
        g_colf[rowA] = make_float2(expf(f2a), expf(0.2f * f2a));
        g_rowf[rowB] = make_float2(expf(f1b), expf(0.2f * f1b));
        g_colf[rowB] = make_float2(expf(f2b), expf(0.2f * f2b));
    }

    // scatter B fragments (global-s layout): h[row][n] -> g_Bf[((s*8+f)*32+l)*2+half]
#pragma unroll
    for (int pass = 0; pass < 2; pass++) {
        int row = pass ? rowB : rowA;
        const float* av = pass ? acc1 : acc0;
        int s = row >> 3;
        int l_lo = row & 3;
        int half = (row >> 2) & 1;
#pragma unroll
        for (int j = 0; j < 4; j++) {
            int n = cg + j;
            int f = n >> 3;
            int l = ((n & 7) << 2) | l_lo;
            g_Bf[(((size_t)(s * 8 + f) * 32 + l) << 1) + half] = f2tf32(av[j]);
        }
    }
}

// ---------------- main kernel ----------------
// grid 256 x 128 threads: rb = blockIdx & 63 (row block of 128), split = blockIdx >> 6.
// 4 warps x 32 rows. Register-software-pipelined s-loop. P fed to MMA as raw
// fp32 bits (HW tf32 truncation). Denominator computed by a 9th MMA per
// rowfrag with B = ones (row sums land in d0/d2; no FADD chain, no shuffles).
__global__ void __launch_bounds__(128, 2) k_main(const int* __restrict__ adj) {
    extern __shared__ char sm[];
    uint32_t sb = smem_u32(sm);

    int tid = threadIdx.x;
    int wid = tid >> 5;     // 0..3
    int lane = tid & 31;
    int g = lane >> 2;
    int c = lane & 3;

    int rb = blockIdx.x & 63;
    int split = blockIdx.x >> 6;
    int row0 = rb * M_CTA;
    int K0base = split * KSPLIT;

    float e1r[4], e1br[4];
#pragma unroll
    for (int q = 0; q < 4; q++) {
        float2 rf = g_rowf[row0 + wid * 32 + g + q * 8];
        e1r[q] = rf.x; e1br[q] = rf.y;
    }

    float acc[2][8][4];
#pragma unroll
    for (int i = 0; i < 2; i++)
#pragma unroll
        for (int f = 0; f < 8; f++)
#pragma unroll
            for (int q = 0; q < 4; q++) acc[i][f][q] = 0.f;

    float dacc[2][4];
#pragma unroll
    for (int i = 0; i < 2; i++)
#pragma unroll
        for (int q = 0; q < 4; q++) dacc[i][q] = 0.f;

    const uint32_t adjOff[2] = {OFF_ADJ0, OFF_ADJ1};
    const uint32_t bfOff[2] = {OFF_BF0, OFF_BF1};
    const uint32_t cfOff[2] = {OFF_CF0, OFF_CF1};
    const uint32_t bone = 0x3F800000u;   // 1.0f, exact in tf32

    auto prefetch = [&](int chunk, int buf) {
        int K0 = K0base + chunk * KCHUNK;
        int jr = tid & 15;
        int rbase = tid >> 4;       // 0..7
        const char* srcbase = (const char*)(adj + (size_t)row0 * NN + K0) + jr * 16;
        uint32_t dstbase = sb + adjOff[buf] + jr * 16;
#pragma unroll
        for (int pass = 0; pass < 16; pass++) {
            int row = pass * 8 + rbase;
            CP16(dstbase + row * ADJ_STRIDE, srcbase + (size_t)row * (NN * 4));
        }
        const char* bsrc = (const char*)g_Bf + (size_t)K0 * 256;
        uint32_t bdst = sb + bfOff[buf];
#pragma unroll
        for (int p = 0; p < 8; p++) {
            int piece = tid + p * 128;
            CP16(bdst + piece * 16, bsrc + piece * 16);
        }
        if (tid < 32) {
            CP16(sb + cfOff[buf] + tid * 16, (const char*)(g_colf + K0 + tid * 2));
        }
    };

    prefetch(0, 0); CP_COMMIT();
    prefetch(1, 1); CP_COMMIT();

    for (int it = 0; it < NCHUNK; ++it) {
        int buf = it & 1;
        CP_WAIT1();
        __syncthreads();

        const char* adjS = sm + adjOff[buf];
        const uint32_t* bS = (const uint32_t*)(sm + bfOff[buf]);
        const float2* cfS = (const float2*)(sm + cfOff[buf]);

        // ---- register software pipeline: stage s+1 loads ahead of s compute ----
        float2 rc0[2], rc4[2];
        int ra[2][8];
        uint32_t rbf[2][16];

        // prologue: stage s = 0
        rc0[0] = cfS[c];
        rc4[0] = cfS[c + 4];
#pragma unroll
        for (int q = 0; q < 4; q++) {
            int row = wid * 32 + g + q * 8;
            const int* ar = (const int*)(adjS + row * ADJ_STRIDE) + c;
            ra[0][2 * q] = ar[0];
            ra[0][2 * q + 1] = ar[4];
        }
#pragma unroll
        for (int f = 0; f < 8; f++) {
            uint32_t boff = (f * 32 + lane) * 2;
            rbf[0][2 * f] = bS[boff];
            rbf[0][2 * f + 1] = bS[boff + 1];
        }

#pragma unroll
        for (int s = 0; s < 8; s++) {
            int cur = s & 1, nxt = cur ^ 1;
            if (s < 7) {
                rc0[nxt] = cfS[(s + 1) * 8 + c];
                rc4[nxt] = cfS[(s + 1) * 8 + c + 4];
#pragma unroll
                for (int q = 0; q < 4; q++) {
                    int row = wid * 32 + g + q * 8;
                    const int* ar = (const int*)(adjS + row * ADJ_STRIDE) + (s + 1) * 8 + c;
                    ra[nxt][2 * q] = ar[0];
                    ra[nxt][2 * q + 1] = ar[4];
                }
#pragma unroll
                for (int f = 0; f < 8; f++) {
                    uint32_t boff = (((s + 1) * 8 + f) * 32 + lane) * 2;
                    rbf[nxt][2 * f] = bS[boff];
                    rbf[nxt][2 * f + 1] = bS[boff + 1];
                }
            }

            float2 c0 = rc0[cur], c4 = rc4[cur];
            uint32_t afrag[2][4];
#pragma unroll
            for (int q = 0; q < 4; q++) {
                int ad0 = ra[cur][2 * q];
                int ad4 = ra[cur][2 * q + 1];
                float p0 = fmaxf(e1r[q] * c0.x, e1br[q] * c0.y);
                float p4 = fmaxf(e1r[q] * c4.x, e1br[q] * c4.y);
                p0 = (ad0 != 0) ? p0 : 0.f;
                p4 = (ad4 != 0) ? p4 : 0.f;
                afrag[q >> 1][(q & 1) + 0] = __float_as_uint(p0);
                afrag[q >> 1][(q & 1) + 2] = __float_as_uint(p4);
            }

#pragma unroll
            for (int f = 0; f < 8; f++) {
                uint32_t b0 = rbf[cur][2 * f];
                uint32_t b1 = rbf[cur][2 * f + 1];
                mma_tf32(acc[0][f][0], acc[0][f][1], acc[0][f][2], acc[0][f][3],
                         afrag[0][0], afrag[0][1], afrag[0][2], afrag[0][3], b0, b1);
                mma_tf32(acc[1][f][0], acc[1][f][1], acc[1][f][2], acc[1][f][3],
                         afrag[1][0], afrag[1][1], afrag[1][2], afrag[1][3], b0, b1);
            }
            // denominator MMA: B = ones -> every output column = row sum of P
            mma_tf32(dacc[0][0], dacc[0][1], dacc[0][2], dacc[0][3],
                     afrag[0][0], afrag[0][1], afrag[0][2], afrag[0][3], bone, bone);
            mma_tf32(dacc[1][0], dacc[1][1], dacc[1][2], dacc[1][3],
                     afrag[1][0], afrag[1][1], afrag[1][2], afrag[1][3], bone, bone);
        }

        __syncthreads();
        if (it + 2 < NCHUNK) prefetch(it + 2, buf);
        CP_COMMIT();
    }

    // ---- epilogue: numerators ----
#pragma unroll
    for (int rf = 0; rf < 2; rf++) {
        int m0 = row0 + wid * 32 + rf * 16 + g;
#pragma unroll
        for (int f = 0; f < 8; f++) {
            int col = f * 8 + c * 2;
            *(float2*)&g_num[split][(size_t)m0 * OUTF + col] =
                make_float2(acc[rf][f][0], acc[rf][f][1]);
            *(float2*)&g_num[split][(size_t)(m0 + 8) * OUTF + col] =
                make_float2(acc[rf][f][2], acc[rf][f][3]);
        }
    }

    // ---- denominators: d0 = row g sum, d2 = row g+8 sum (all cols equal) ----
    if (c == 0) {
#pragma unroll
        for (int rf = 0; rf < 2; rf++) {
            int m0 = row0 + wid * 32 + rf * 16 + g;
            g_den[split][m0] = dacc[rf][0];
            g_den[split][m0 + 8] = dacc[rf][2];
        }
    }
}

// ---------------- combine partials, divide, elu ----------------
__global__ void __launch_bounds__(256) k_comb(float* __restrict__ out) {
    int idx = blockIdx.x * 256 + threadIdx.x;  // over NN*OUTF
    int row = idx >> 6;
    float num = 0.f, den = 0.f;
#pragma unroll
    for (int p = 0; p < NSPLIT; p++) {
        num += g_num[p][idx];
        den += g_den[p][row];
    }
    float v = num / den;
    out[idx] = v > 0.f ? v : expm1f(v);
}

// ---------------- launch ----------------
#define PRE_SMEM (INF_ * OUTF * 4 + 32 * INF_ * 4 + 2 * OUTF * 4)  // 49664

extern "C" void kernel_launch(void* const* d_in, const int* in_sizes, int n_in,
                              void* d_out, int out_size) {
    const float* X = (const float*)d_in[0];
    const int* adj = (const int*)d_in[1];
    const float* W = (const float*)d_in[2];
    const float* a = (const float*)d_in[3];
    float* out = (float*)d_out;

    cudaFuncSetAttribute(k_pre, cudaFuncAttributeMaxDynamicSharedMemorySize, PRE_SMEM);
    cudaFuncSetAttribute(k_main, cudaFuncAttributeMaxDynamicSharedMemorySize, SMEM_BYTES);

    k_pre<<<NN / 32, 256, PRE_SMEM>>>(X, W, a);
    k_main<<<256, 128, SMEM_BYTES>>>(adj);
    k_comb<<<(NN * OUTF) / 256, 256>>>(out);
}